// round 11
// baseline (speedup 1.0000x reference)
#include <cuda_runtime.h>
#include <cuda_bf16.h>
#include <stdint.h>

#define D 128
#define E_CAP 16384
#define N_CAP 65536
#define NNZ_CAP (1 << 20)
#define EPS 1e-8f
#define CHUNK 4096
#define NBLK_E (E_CAP / CHUNK)            // 4
#define NBLK_N (N_CAP / CHUNK)            // 16

// ---------------- scratch (static device globals; no allocation) ------------
__device__ float    g_xnode[(size_t)N_CAP * D];      // fp32 x@W^T (exact residual)
__device__ unsigned g_xnode_h[(size_t)N_CAP * 64];   // bf16x2 gather mirror
__device__ unsigned g_heattr_h[(size_t)E_CAP * 64];  // bf16x2 hyperedge attr
__device__ int g_eidx[NNZ_CAP];
__device__ int g_nidx[NNZ_CAP];
__device__ int g_eoff[E_CAP + 1];
__device__ int g_noff[N_CAP + 1];
__device__ int g_cnts[E_CAP + N_CAP];                // counts, then reused as cursors
__device__ int g_bsum[NBLK_E + NBLK_N];
__device__ int g_is64;

#define ECNT (g_cnts)
#define NCNT (g_cnts + E_CAP)

// ---------------- init: zero counters + index dtype detect -------------------
__global__ void init_kernel(const int* __restrict__ h) {
    int i = blockIdx.x * blockDim.x + threadIdx.x;
    ((int4*)g_cnts)[i] = make_int4(0, 0, 0, 0);
    if (i == 0)
        g_is64 = (h[1] == 0 && h[3] == 0 && h[5] == 0 && h[7] == 0) ? 1 : 0;
}

// ---------------- histograms (4 entries / thread), per side ------------------
__global__ __launch_bounds__(256) void hist_e_kernel(const void* __restrict__ base, int nnz) {
    int i0 = (blockIdx.x * blockDim.x + threadIdx.x) * 4;
    if (i0 >= nnz) return;
    int m = nnz - i0; if (m > 4) m = 4;
    int e[4];
    if (g_is64) {
        const long long* p = (const long long*)base + nnz;
        #pragma unroll
        for (int k = 0; k < 4; k++) e[k] = (int)__ldg(p + i0 + ((k < m) ? k : 0));
    } else {
        const int* p = (const int*)base + nnz;
        #pragma unroll
        for (int k = 0; k < 4; k++) e[k] = __ldg(p + i0 + ((k < m) ? k : 0));
    }
    #pragma unroll
    for (int k = 0; k < 4; k++)
        if (k < m) atomicAdd(&ECNT[e[k]], 1);
}

__global__ __launch_bounds__(256) void hist_n_kernel(const void* __restrict__ base, int nnz) {
    int i0 = (blockIdx.x * blockDim.x + threadIdx.x) * 4;
    if (i0 >= nnz) return;
    int m = nnz - i0; if (m > 4) m = 4;
    int s[4];
    if (g_is64) {
        const long long* p = (const long long*)base;
        #pragma unroll
        for (int k = 0; k < 4; k++) s[k] = (int)__ldg(p + i0 + ((k < m) ? k : 0));
    } else {
        const int* p = (const int*)base;
        #pragma unroll
        for (int k = 0; k < 4; k++) s[k] = __ldg(p + i0 + ((k < m) ? k : 0));
    }
    #pragma unroll
    for (int k = 0; k < 4; k++)
        if (k < m) atomicAdd(&NCNT[s[k]], 1);
}

// ---------------- 2-level exclusive scan (which: 0=edges, 1=nodes) -----------
__global__ __launch_bounds__(1024) void scan_local_kernel(int which) {
    int b = blockIdx.x;
    const int* cnt; int* off; int* bsum;
    if (which == 0) { cnt = ECNT; off = g_eoff; bsum = g_bsum; }
    else            { cnt = NCNT; off = g_noff; bsum = g_bsum + NBLK_E; }
    int lo = b * CHUNK;

    __shared__ int wsum[32];
    int tid = threadIdx.x, lane = tid & 31, wid = tid >> 5;
    int idx = lo + tid * 4;

    int4 v = *(const int4*)(cnt + idx);
    int tsum = v.x + v.y + v.z + v.w;
    int incl = tsum;
    #pragma unroll
    for (int s = 1; s < 32; s <<= 1) {
        int t = __shfl_up_sync(0xffffffffu, incl, s);
        if (lane >= s) incl += t;
    }
    if (lane == 31) wsum[wid] = incl;
    __syncthreads();
    if (wid == 0) {
        int w = wsum[lane];
        int wi = w;
        #pragma unroll
        for (int s = 1; s < 32; s <<= 1) {
            int t = __shfl_up_sync(0xffffffffu, wi, s);
            if (lane >= s) wi += t;
        }
        wsum[lane] = wi - w;
    }
    __syncthreads();
    int ex = wsum[wid] + incl - tsum;
    off[idx]     = ex;
    off[idx + 1] = ex + v.x;
    off[idx + 2] = ex + v.x + v.y;
    off[idx + 3] = ex + v.x + v.y + v.z;
    if (tid == 1023) bsum[b] = ex + tsum;
}

// fixup adds cross-block base AND initializes cursors (= start offsets)
__global__ __launch_bounds__(1024) void scan_fixup_kernel(int which) {
    int b = blockIdx.x;
    int* off; int* cur; const int* bsum; int nblk; int ncap;
    if (which == 0) { off = g_eoff; cur = ECNT; bsum = g_bsum;          nblk = NBLK_E; ncap = E_CAP; }
    else            { off = g_noff; cur = NCNT; bsum = g_bsum + NBLK_E; nblk = NBLK_N; ncap = N_CAP; }

    __shared__ int s_base;
    int tid = threadIdx.x;
    if (tid == 0) {
        int base = 0;
        for (int i = 0; i < b; i++) base += bsum[i];
        s_base = base;
    }
    __syncthreads();
    int base = s_base;
    int idx = b * CHUNK + tid * 4;
    int4 o = *(int4*)(off + idx);
    o.x += base; o.y += base; o.z += base; o.w += base;
    *(int4*)(off + idx) = o;
    *(int4*)(cur + idx) = o;   // cursors start at segment start
    if (tid == 0 && b == nblk - 1) off[ncap] = base + bsum[b];
}

// ---------------- bucket fills (cursor atomics, 4/thread), per side ----------
__global__ __launch_bounds__(256) void fill_e_kernel(const void* __restrict__ base, int nnz) {
    int i0 = (blockIdx.x * blockDim.x + threadIdx.x) * 4;
    if (i0 >= nnz) return;
    int m = nnz - i0; if (m > 4) m = 4;
    int src[4], e[4];
    if (g_is64) {
        const long long* p = (const long long*)base;
        #pragma unroll
        for (int k = 0; k < 4; k++) {
            int i = i0 + ((k < m) ? k : 0);
            src[k] = (int)__ldg(p + i);
            e[k]   = (int)__ldg(p + nnz + i);
        }
    } else {
        const int* p = (const int*)base;
        #pragma unroll
        for (int k = 0; k < 4; k++) {
            int i = i0 + ((k < m) ? k : 0);
            src[k] = __ldg(p + i);
            e[k]   = __ldg(p + nnz + i);
        }
    }
    #pragma unroll
    for (int k = 0; k < 4; k++) {
        if (k < m) {
            int pe = atomicAdd(&ECNT[e[k]], 1);
            g_eidx[pe] = src[k];
        }
    }
}

__global__ __launch_bounds__(256) void fill_n_kernel(const void* __restrict__ base, int nnz) {
    int i0 = (blockIdx.x * blockDim.x + threadIdx.x) * 4;
    if (i0 >= nnz) return;
    int m = nnz - i0; if (m > 4) m = 4;
    int src[4], e[4];
    if (g_is64) {
        const long long* p = (const long long*)base;
        #pragma unroll
        for (int k = 0; k < 4; k++) {
            int i = i0 + ((k < m) ? k : 0);
            src[k] = (int)__ldg(p + i);
            e[k]   = (int)__ldg(p + nnz + i);
        }
    } else {
        const int* p = (const int*)base;
        #pragma unroll
        for (int k = 0; k < 4; k++) {
            int i = i0 + ((k < m) ? k : 0);
            src[k] = __ldg(p + i);
            e[k]   = __ldg(p + nnz + i);
        }
    }
    #pragma unroll
    for (int k = 0; k < 4; k++) {
        if (k < m) {
            int pn = atomicAdd(&NCNT[src[k]], 1);
            g_nidx[pn] = e[k];
        }
    }
}

// ---------------- GEMM: g_xnode = x @ W^T, 128x128 tile, 8x8/thread ----------
#define WT_STRIDE 132
#define GEMM_SMEM ((128 * WT_STRIDE + 128 * WT_STRIDE) * 4)   // 135168 B

__device__ __forceinline__ unsigned long long fma2(unsigned long long a,
                                                   unsigned long long b,
                                                   unsigned long long c) {
    unsigned long long d;
    asm("fma.rn.f32x2 %0, %1, %2, %3;" : "=l"(d) : "l"(a), "l"(b), "l"(c));
    return d;
}

__global__ __launch_bounds__(256, 1) void gemm_kernel(const float* __restrict__ x,
                                                      const float* __restrict__ W,
                                                      int N) {
    extern __shared__ float sm[];
    float* WT = sm;                        // [128][132], WT[k][j] = W[j][k]
    float* Xs = sm + 128 * WT_STRIDE;      // [128][132]

    int t = threadIdx.x;
    int row0 = blockIdx.x * 128;

    #pragma unroll
    for (int i = 0; i < 64; i++) {
        int idx = t + i * 256;
        int j = idx >> 7, k = idx & 127;
        WT[k * WT_STRIDE + j] = W[idx];
    }
    #pragma unroll
    for (int i = 0; i < 64; i++) {
        int idx = t + i * 256;
        int r = idx >> 7, k = idx & 127;
        int row = row0 + r;
        if (row >= N) row = N - 1;
        Xs[r * WT_STRIDE + k] = x[(size_t)row * D + k];
    }
    __syncthreads();

    int tx = t & 15, ty = t >> 4;
    int c0 = tx * 8, r0 = ty * 8;

    unsigned long long acc[8][4];
    #pragma unroll
    for (int i = 0; i < 8; i++)
        #pragma unroll
        for (int j = 0; j < 4; j++) acc[i][j] = 0ull;

    #pragma unroll 2
    for (int k = 0; k < 128; k++) {
        ulonglong2 wa = *(const ulonglong2*)(WT + k * WT_STRIDE + c0);
        ulonglong2 wb = *(const ulonglong2*)(WT + k * WT_STRIDE + c0 + 4);
        #pragma unroll
        for (int i = 0; i < 8; i++) {
            unsigned au = __float_as_uint(Xs[(r0 + i) * WT_STRIDE + k]);
            unsigned long long aa;
            asm("mov.b64 %0, {%1, %1};" : "=l"(aa) : "r"(au));
            acc[i][0] = fma2(aa, wa.x, acc[i][0]);
            acc[i][1] = fma2(aa, wa.y, acc[i][1]);
            acc[i][2] = fma2(aa, wb.x, acc[i][2]);
            acc[i][3] = fma2(aa, wb.y, acc[i][3]);
        }
    }

    #pragma unroll
    for (int i = 0; i < 8; i++) {
        int row = row0 + r0 + i;
        if (row < N) {
            ulonglong2 o0; o0.x = acc[i][0]; o0.y = acc[i][1];
            ulonglong2 o1; o1.x = acc[i][2]; o1.y = acc[i][3];
            *(ulonglong2*)(g_xnode + (size_t)row * D + c0)     = o0;
            *(ulonglong2*)(g_xnode + (size_t)row * D + c0 + 4) = o1;
            uint4 h;
            #pragma unroll
            for (int j = 0; j < 4; j++) {
                unsigned lo, hi;
                asm("mov.b64 {%0, %1}, %2;" : "=r"(lo), "=r"(hi) : "l"(acc[i][j]));
                unsigned r2;
                asm("cvt.rn.bf16x2.f32 %0, %1, %2;" : "=r"(r2)
                    : "f"(__uint_as_float(hi)), "f"(__uint_as_float(lo)));
                ((unsigned*)&h)[j] = r2;
            }
            *(uint4*)(g_xnode_h + (size_t)row * 64 + tx * 4) = h;
        }
    }
}

// ---------------- phase A: 2 warps/edge (feature split), unroll-4 ------------
__global__ __launch_bounds__(256) void edge_agg_kernel() {
    int gw = (blockIdx.x * blockDim.x + threadIdx.x) >> 5;
    int e = gw >> 1;                    // edge id
    int half = gw & 1;                  // feature half (32 bf16x2 each)
    int lane = threadIdx.x & 31;
    int beg = g_eoff[e], end = g_eoff[e + 1];
    if (beg == end) return;

    const unsigned* src = g_xnode_h + half * 32 + lane;  // + n*64 per member
    float2 a0 = make_float2(0.f, 0.f);
    float2 a1 = make_float2(0.f, 0.f);

    for (int base = beg; base < end; base += 32) {
        int cnt = end - base; if (cnt > 32) cnt = 32;
        int myi = g_eidx[base + ((lane < cnt) ? lane : 0)];
        int k = 0;
        for (; k + 4 <= cnt; k += 4) {
            int n0 = __shfl_sync(0xffffffffu, myi, k);
            int n1 = __shfl_sync(0xffffffffu, myi, k + 1);
            int n2 = __shfl_sync(0xffffffffu, myi, k + 2);
            int n3 = __shfl_sync(0xffffffffu, myi, k + 3);
            unsigned u0 = src[(size_t)n0 * 64];
            unsigned u1 = src[(size_t)n1 * 64];
            unsigned u2 = src[(size_t)n2 * 64];
            unsigned u3 = src[(size_t)n3 * 64];
            a0.x += __uint_as_float(u0 << 16);
            a0.y += __uint_as_float(u0 & 0xffff0000u);
            a1.x += __uint_as_float(u1 << 16);
            a1.y += __uint_as_float(u1 & 0xffff0000u);
            a0.x += __uint_as_float(u2 << 16);
            a0.y += __uint_as_float(u2 & 0xffff0000u);
            a1.x += __uint_as_float(u3 << 16);
            a1.y += __uint_as_float(u3 & 0xffff0000u);
        }
        for (; k < cnt; k++) {
            int n0 = __shfl_sync(0xffffffffu, myi, k);
            unsigned u0 = src[(size_t)n0 * 64];
            a0.x += __uint_as_float(u0 << 16);
            a0.y += __uint_as_float(u0 & 0xffff0000u);
        }
    }

    float inv = 1.0f / ((float)(end - beg) + EPS);
    float f0 = (a0.x + a1.x) * inv;
    float f1 = (a0.y + a1.y) * inv;
    unsigned r;
    asm("cvt.rn.bf16x2.f32 %0, %1, %2;" : "=r"(r) : "f"(f1), "f"(f0));
    g_heattr_h[(size_t)e * 64 + half * 32 + lane] = r;
}

// ---------------- phase B: warp-per-node, unroll-4, fused finalize -----------
__global__ __launch_bounds__(256) void node_agg_kernel(const float* __restrict__ bias,
                                                       float* __restrict__ out,
                                                       int N) {
    int w = (blockIdx.x * blockDim.x + threadIdx.x) >> 5;
    if (w >= N) return;
    int lane = threadIdx.x & 31;
    int beg = g_noff[w], end = g_noff[w + 1];

    float4 a0 = make_float4(0.f, 0.f, 0.f, 0.f);
    float4 a1 = make_float4(0.f, 0.f, 0.f, 0.f);

    for (int base = beg; base < end; base += 32) {
        int cnt = end - base; if (cnt > 32) cnt = 32;
        int myi = g_nidx[base + ((lane < cnt) ? lane : 0)];
        int k = 0;
        for (; k + 4 <= cnt; k += 4) {
            int e0 = __shfl_sync(0xffffffffu, myi, k);
            int e1 = __shfl_sync(0xffffffffu, myi, k + 1);
            int e2 = __shfl_sync(0xffffffffu, myi, k + 2);
            int e3 = __shfl_sync(0xffffffffu, myi, k + 3);
            uint2 u0 = *(const uint2*)(g_heattr_h + (size_t)e0 * 64 + lane * 2);
            uint2 u1 = *(const uint2*)(g_heattr_h + (size_t)e1 * 64 + lane * 2);
            uint2 u2 = *(const uint2*)(g_heattr_h + (size_t)e2 * 64 + lane * 2);
            uint2 u3 = *(const uint2*)(g_heattr_h + (size_t)e3 * 64 + lane * 2);
            a0.x += __uint_as_float(u0.x << 16);
            a0.y += __uint_as_float(u0.x & 0xffff0000u);
            a0.z += __uint_as_float(u0.y << 16);
            a0.w += __uint_as_float(u0.y & 0xffff0000u);
            a1.x += __uint_as_float(u1.x << 16);
            a1.y += __uint_as_float(u1.x & 0xffff0000u);
            a1.z += __uint_as_float(u1.y << 16);
            a1.w += __uint_as_float(u1.y & 0xffff0000u);
            a0.x += __uint_as_float(u2.x << 16);
            a0.y += __uint_as_float(u2.x & 0xffff0000u);
            a0.z += __uint_as_float(u2.y << 16);
            a0.w += __uint_as_float(u2.y & 0xffff0000u);
            a1.x += __uint_as_float(u3.x << 16);
            a1.y += __uint_as_float(u3.x & 0xffff0000u);
            a1.z += __uint_as_float(u3.y << 16);
            a1.w += __uint_as_float(u3.y & 0xffff0000u);
        }
        for (; k < cnt; k++) {
            int e0 = __shfl_sync(0xffffffffu, myi, k);
            uint2 u0 = *(const uint2*)(g_heattr_h + (size_t)e0 * 64 + lane * 2);
            a0.x += __uint_as_float(u0.x << 16);
            a0.y += __uint_as_float(u0.x & 0xffff0000u);
            a0.z += __uint_as_float(u0.y << 16);
            a0.w += __uint_as_float(u0.y & 0xffff0000u);
        }
    }

    float s = 1.0f / ((float)(end - beg) + EPS);
    float4 xn = ((const float4*)g_xnode)[(size_t)w * 32 + lane];
    float4 b  = ((const float4*)bias)[lane];
    float4 o;
    o.x = (a0.x + a1.x) * s + xn.x + b.x;
    o.y = (a0.y + a1.y) * s + xn.y + b.y;
    o.z = (a0.z + a1.z) * s + xn.z + b.z;
    o.w = (a0.w + a1.w) * s + xn.w + b.w;
    ((float4*)out)[(size_t)w * 32 + lane] = o;
}

// ---------------- launch -----------------------------------------------------
extern "C" void kernel_launch(void* const* d_in, const int* in_sizes, int n_in,
                              void* d_out, int out_size) {
    const float* x    = (const float*)d_in[0];
    const void*  hidx = d_in[1];
    const float* W    = (const float*)d_in[2];
    const float* bias = (const float*)d_in[3];
    float* out = (float*)d_out;

    int N   = in_sizes[0] / D;
    int nnz = in_sizes[1] / 2;
    int q = (nnz + 3) / 4;

    static cudaStream_t s2 = 0, s3 = 0;
    static cudaEvent_t evA = 0, evI = 0, evG = 0, evN = 0;
    if (!s2) {
        cudaStreamCreateWithFlags(&s2, cudaStreamNonBlocking);
        cudaStreamCreateWithFlags(&s3, cudaStreamNonBlocking);
        cudaEventCreateWithFlags(&evA, cudaEventDisableTiming);
        cudaEventCreateWithFlags(&evI, cudaEventDisableTiming);
        cudaEventCreateWithFlags(&evG, cudaEventDisableTiming);
        cudaEventCreateWithFlags(&evN, cudaEventDisableTiming);
        cudaFuncSetAttribute(gemm_kernel,
                             cudaFuncAttributeMaxDynamicSharedMemorySize, GEMM_SMEM);
    }

    // fork GEMM immediately
    cudaEventRecord(evA, 0);
    cudaStreamWaitEvent(s2, evA, 0);
    gemm_kernel<<<(N + 127) / 128, 256, GEMM_SMEM, s2>>>(x, W, N);
    cudaEventRecord(evG, s2);

    // shared init (counters + dtype flag), then fork node-side CSR to s3
    init_kernel<<<(E_CAP + N_CAP) / 4 / 256, 256>>>((const int*)hidx);
    cudaEventRecord(evI, 0);
    cudaStreamWaitEvent(s3, evI, 0);

    // node-side CSR on s3 (off the critical path)
    hist_n_kernel<<<(q + 255) / 256, 256, 0, s3>>>(hidx, nnz);
    scan_local_kernel<<<NBLK_N, 1024, 0, s3>>>(1);
    scan_fixup_kernel<<<NBLK_N, 1024, 0, s3>>>(1);
    fill_n_kernel<<<(q + 255) / 256, 256, 0, s3>>>(hidx, nnz);
    cudaEventRecord(evN, s3);

    // edge-side CSR on capture stream -> edge_agg as early as possible
    hist_e_kernel<<<(q + 255) / 256, 256>>>(hidx, nnz);
    scan_local_kernel<<<NBLK_E, 1024>>>(0);
    scan_fixup_kernel<<<NBLK_E, 1024>>>(0);
    fill_e_kernel<<<(q + 255) / 256, 256>>>(hidx, nnz);
    edge_agg_kernel<<<E_CAP / 4, 256>>>();                 // 2 warps per edge

    // node_agg needs: heattr (done), node CSR (evN), residual (evG)
    cudaStreamWaitEvent(0, evN, 0);
    cudaStreamWaitEvent(0, evG, 0);
    node_agg_kernel<<<(N + 7) / 8, 256>>>(bias, out, N);
}

// round 12
// speedup vs baseline: 1.0290x; 1.0290x over previous
#include <cuda_runtime.h>
#include <cuda_bf16.h>
#include <stdint.h>

#define D 128
#define E_CAP 16384
#define N_CAP 65536
#define NNZ_CAP (1 << 20)
#define EPS 1e-8f

// ---------------- scratch (static device globals; no allocation) ------------
__device__ float    g_xnode[(size_t)N_CAP * D];      // fp32 x@W^T (exact residual)
__device__ unsigned g_xnode_h[(size_t)N_CAP * 64];   // bf16x2 gather mirror
__device__ unsigned g_heattr_h[(size_t)E_CAP * 64];  // bf16x2 hyperedge attr
__device__ int g_eidx[NNZ_CAP];
__device__ int g_nidx[NNZ_CAP];
__device__ int g_eoff[E_CAP + 1];
__device__ int g_noff[N_CAP + 1];
__device__ int g_cnts[E_CAP + N_CAP];                // counts, then reused as cursors
__device__ int g_is64;

#define ECNT (g_cnts)
#define NCNT (g_cnts + E_CAP)

// ---------------- inits: zero counters (per side) + dtype detect -------------
__global__ void init_e_kernel(const int* __restrict__ h) {
    int i = blockIdx.x * blockDim.x + threadIdx.x;
    ((int4*)ECNT)[i] = make_int4(0, 0, 0, 0);
    if (i == 0)
        g_is64 = (h[1] == 0 && h[3] == 0 && h[5] == 0 && h[7] == 0) ? 1 : 0;
}

__global__ void init_n_kernel() {
    int i = blockIdx.x * blockDim.x + threadIdx.x;
    ((int4*)NCNT)[i] = make_int4(0, 0, 0, 0);
}

// ---------------- histograms (4 entries / thread), per side ------------------
__global__ __launch_bounds__(256) void hist_e_kernel(const void* __restrict__ base, int nnz) {
    int i0 = (blockIdx.x * blockDim.x + threadIdx.x) * 4;
    if (i0 >= nnz) return;
    int m = nnz - i0; if (m > 4) m = 4;
    int e[4];
    if (g_is64) {
        const long long* p = (const long long*)base + nnz;
        #pragma unroll
        for (int k = 0; k < 4; k++) e[k] = (int)__ldg(p + i0 + ((k < m) ? k : 0));
    } else {
        const int* p = (const int*)base + nnz;
        #pragma unroll
        for (int k = 0; k < 4; k++) e[k] = __ldg(p + i0 + ((k < m) ? k : 0));
    }
    #pragma unroll
    for (int k = 0; k < 4; k++)
        if (k < m) atomicAdd(&ECNT[e[k]], 1);
}

__global__ __launch_bounds__(256) void hist_n_kernel(const void* __restrict__ base, int nnz) {
    int i0 = (blockIdx.x * blockDim.x + threadIdx.x) * 4;
    if (i0 >= nnz) return;
    int m = nnz - i0; if (m > 4) m = 4;
    int s[4];
    if (g_is64) {
        const long long* p = (const long long*)base;
        #pragma unroll
        for (int k = 0; k < 4; k++) s[k] = (int)__ldg(p + i0 + ((k < m) ? k : 0));
    } else {
        const int* p = (const int*)base;
        #pragma unroll
        for (int k = 0; k < 4; k++) s[k] = __ldg(p + i0 + ((k < m) ? k : 0));
    }
    #pragma unroll
    for (int k = 0; k < 4; k++)
        if (k < m) atomicAdd(&NCNT[s[k]], 1);
}

// ---------------- fused single-block exclusive scan (+ cursor init) ----------
// SEG ints per thread, 1024 threads, one block. off gets exclusive prefix,
// cur mirrors it (cursors), off[count] gets total.
template <int SEG>
__global__ __launch_bounds__(1024) void scan_fused_kernel(const int* __restrict__ cnt,
                                                          int* __restrict__ off,
                                                          int* __restrict__ cur,
                                                          int count) {
    __shared__ int wsum[32];
    int tid = threadIdx.x, lane = tid & 31, wid = tid >> 5;
    int base = tid * SEG;

    int v[SEG];
    #pragma unroll
    for (int i = 0; i < SEG / 4; i++)
        *(int4*)(v + i * 4) = *(const int4*)(cnt + base + i * 4);

    int tsum = 0;
    #pragma unroll
    for (int i = 0; i < SEG; i++) tsum += v[i];

    int incl = tsum;
    #pragma unroll
    for (int s = 1; s < 32; s <<= 1) {
        int t = __shfl_up_sync(0xffffffffu, incl, s);
        if (lane >= s) incl += t;
    }
    if (lane == 31) wsum[wid] = incl;
    __syncthreads();
    if (wid == 0) {
        int w = wsum[lane];
        int wi = w;
        #pragma unroll
        for (int s = 1; s < 32; s <<= 1) {
            int t = __shfl_up_sync(0xffffffffu, wi, s);
            if (lane >= s) wi += t;
        }
        wsum[lane] = wi - w;
    }
    __syncthreads();
    int ex = wsum[wid] + incl - tsum;   // exclusive prefix for this thread's seg

    int o[SEG];
    int run = ex;
    #pragma unroll
    for (int i = 0; i < SEG; i++) { o[i] = run; run += v[i]; }

    #pragma unroll
    for (int i = 0; i < SEG / 4; i++) {
        int4 w4 = *(int4*)(o + i * 4);
        *(int4*)(off + base + i * 4) = w4;
        *(int4*)(cur + base + i * 4) = w4;
    }
    if (tid == 1023) off[count] = run;
}

// ---------------- bucket fills (cursor atomics, 4/thread), per side ----------
__global__ __launch_bounds__(256) void fill_e_kernel(const void* __restrict__ base, int nnz) {
    int i0 = (blockIdx.x * blockDim.x + threadIdx.x) * 4;
    if (i0 >= nnz) return;
    int m = nnz - i0; if (m > 4) m = 4;
    int src[4], e[4];
    if (g_is64) {
        const long long* p = (const long long*)base;
        #pragma unroll
        for (int k = 0; k < 4; k++) {
            int i = i0 + ((k < m) ? k : 0);
            src[k] = (int)__ldg(p + i);
            e[k]   = (int)__ldg(p + nnz + i);
        }
    } else {
        const int* p = (const int*)base;
        #pragma unroll
        for (int k = 0; k < 4; k++) {
            int i = i0 + ((k < m) ? k : 0);
            src[k] = __ldg(p + i);
            e[k]   = __ldg(p + nnz + i);
        }
    }
    #pragma unroll
    for (int k = 0; k < 4; k++) {
        if (k < m) {
            int pe = atomicAdd(&ECNT[e[k]], 1);
            g_eidx[pe] = src[k];
        }
    }
}

__global__ __launch_bounds__(256) void fill_n_kernel(const void* __restrict__ base, int nnz) {
    int i0 = (blockIdx.x * blockDim.x + threadIdx.x) * 4;
    if (i0 >= nnz) return;
    int m = nnz - i0; if (m > 4) m = 4;
    int src[4], e[4];
    if (g_is64) {
        const long long* p = (const long long*)base;
        #pragma unroll
        for (int k = 0; k < 4; k++) {
            int i = i0 + ((k < m) ? k : 0);
            src[k] = (int)__ldg(p + i);
            e[k]   = (int)__ldg(p + nnz + i);
        }
    } else {
        const int* p = (const int*)base;
        #pragma unroll
        for (int k = 0; k < 4; k++) {
            int i = i0 + ((k < m) ? k : 0);
            src[k] = __ldg(p + i);
            e[k]   = __ldg(p + nnz + i);
        }
    }
    #pragma unroll
    for (int k = 0; k < 4; k++) {
        if (k < m) {
            int pn = atomicAdd(&NCNT[src[k]], 1);
            g_nidx[pn] = e[k];
        }
    }
}

// ---------------- GEMM: g_xnode = x @ W^T, 128x128 tile, 8x8/thread ----------
#define WT_STRIDE 132
#define GEMM_SMEM ((128 * WT_STRIDE + 128 * WT_STRIDE) * 4)   // 135168 B

__device__ __forceinline__ unsigned long long fma2(unsigned long long a,
                                                   unsigned long long b,
                                                   unsigned long long c) {
    unsigned long long d;
    asm("fma.rn.f32x2 %0, %1, %2, %3;" : "=l"(d) : "l"(a), "l"(b), "l"(c));
    return d;
}

__global__ __launch_bounds__(256, 1) void gemm_kernel(const float* __restrict__ x,
                                                      const float* __restrict__ W,
                                                      int N) {
    extern __shared__ float sm[];
    float* WT = sm;                        // [128][132], WT[k][j] = W[j][k]
    float* Xs = sm + 128 * WT_STRIDE;      // [128][132]

    int t = threadIdx.x;
    int row0 = blockIdx.x * 128;

    #pragma unroll
    for (int i = 0; i < 64; i++) {
        int idx = t + i * 256;
        int j = idx >> 7, k = idx & 127;
        WT[k * WT_STRIDE + j] = W[idx];
    }
    #pragma unroll
    for (int i = 0; i < 64; i++) {
        int idx = t + i * 256;
        int r = idx >> 7, k = idx & 127;
        int row = row0 + r;
        if (row >= N) row = N - 1;
        Xs[r * WT_STRIDE + k] = x[(size_t)row * D + k];
    }
    __syncthreads();

    int tx = t & 15, ty = t >> 4;
    int c0 = tx * 8, r0 = ty * 8;

    unsigned long long acc[8][4];
    #pragma unroll
    for (int i = 0; i < 8; i++)
        #pragma unroll
        for (int j = 0; j < 4; j++) acc[i][j] = 0ull;

    #pragma unroll 2
    for (int k = 0; k < 128; k++) {
        ulonglong2 wa = *(const ulonglong2*)(WT + k * WT_STRIDE + c0);
        ulonglong2 wb = *(const ulonglong2*)(WT + k * WT_STRIDE + c0 + 4);
        #pragma unroll
        for (int i = 0; i < 8; i++) {
            unsigned au = __float_as_uint(Xs[(r0 + i) * WT_STRIDE + k]);
            unsigned long long aa;
            asm("mov.b64 %0, {%1, %1};" : "=l"(aa) : "r"(au));
            acc[i][0] = fma2(aa, wa.x, acc[i][0]);
            acc[i][1] = fma2(aa, wa.y, acc[i][1]);
            acc[i][2] = fma2(aa, wb.x, acc[i][2]);
            acc[i][3] = fma2(aa, wb.y, acc[i][3]);
        }
    }

    #pragma unroll
    for (int i = 0; i < 8; i++) {
        int row = row0 + r0 + i;
        if (row < N) {
            ulonglong2 o0; o0.x = acc[i][0]; o0.y = acc[i][1];
            ulonglong2 o1; o1.x = acc[i][2]; o1.y = acc[i][3];
            *(ulonglong2*)(g_xnode + (size_t)row * D + c0)     = o0;
            *(ulonglong2*)(g_xnode + (size_t)row * D + c0 + 4) = o1;
            uint4 h;
            #pragma unroll
            for (int j = 0; j < 4; j++) {
                unsigned lo, hi;
                asm("mov.b64 {%0, %1}, %2;" : "=r"(lo), "=r"(hi) : "l"(acc[i][j]));
                unsigned r2;
                asm("cvt.rn.bf16x2.f32 %0, %1, %2;" : "=r"(r2)
                    : "f"(__uint_as_float(hi)), "f"(__uint_as_float(lo)));
                ((unsigned*)&h)[j] = r2;
            }
            *(uint4*)(g_xnode_h + (size_t)row * 64 + tx * 4) = h;
        }
    }
}

// ---------------- bf16x2 pair accumulate helper ------------------------------
__device__ __forceinline__ void acc_bf16x2(float4& a, uint2 u) {
    a.x += __uint_as_float(u.x << 16);
    a.y += __uint_as_float(u.x & 0xffff0000u);
    a.z += __uint_as_float(u.y << 16);
    a.w += __uint_as_float(u.y & 0xffff0000u);
}

// ---------------- phase A: warp-per-edge, shfl-distributed indices (R10) -----
__global__ __launch_bounds__(256) void edge_agg_kernel() {
    int w = (blockIdx.x * blockDim.x + threadIdx.x) >> 5;  // edge id
    int lane = threadIdx.x & 31;
    int beg = g_eoff[w], end = g_eoff[w + 1];
    if (beg == end) return;

    float4 a0 = make_float4(0.f, 0.f, 0.f, 0.f);
    float4 a1 = make_float4(0.f, 0.f, 0.f, 0.f);

    for (int base = beg; base < end; base += 32) {
        int cnt = end - base; if (cnt > 32) cnt = 32;
        int myi = g_eidx[base + ((lane < cnt) ? lane : 0)];
        int k = 0;
        for (; k + 2 <= cnt; k += 2) {
            int n0 = __shfl_sync(0xffffffffu, myi, k);
            int n1 = __shfl_sync(0xffffffffu, myi, k + 1);
            uint2 u0 = *(const uint2*)(g_xnode_h + (size_t)n0 * 64 + lane * 2);
            uint2 u1 = *(const uint2*)(g_xnode_h + (size_t)n1 * 64 + lane * 2);
            acc_bf16x2(a0, u0);
            acc_bf16x2(a1, u1);
        }
        if (k < cnt) {
            int n0 = __shfl_sync(0xffffffffu, myi, k);
            uint2 u0 = *(const uint2*)(g_xnode_h + (size_t)n0 * 64 + lane * 2);
            acc_bf16x2(a0, u0);
        }
    }

    float inv = 1.0f / ((float)(end - beg) + EPS);
    float f0 = (a0.x + a1.x) * inv;
    float f1 = (a0.y + a1.y) * inv;
    float f2 = (a0.z + a1.z) * inv;
    float f3 = (a0.w + a1.w) * inv;
    uint2 r;
    asm("cvt.rn.bf16x2.f32 %0, %1, %2;" : "=r"(r.x) : "f"(f1), "f"(f0));
    asm("cvt.rn.bf16x2.f32 %0, %1, %2;" : "=r"(r.y) : "f"(f3), "f"(f2));
    *(uint2*)(g_heattr_h + (size_t)w * 64 + lane * 2) = r;
}

// ---------------- phase B: warp-per-node, shfl indices + fused finalize (R10)-
__global__ __launch_bounds__(256) void node_agg_kernel(const float* __restrict__ bias,
                                                       float* __restrict__ out,
                                                       int N) {
    int w = (blockIdx.x * blockDim.x + threadIdx.x) >> 5;
    if (w >= N) return;
    int lane = threadIdx.x & 31;
    int beg = g_noff[w], end = g_noff[w + 1];

    float4 a0 = make_float4(0.f, 0.f, 0.f, 0.f);
    float4 a1 = make_float4(0.f, 0.f, 0.f, 0.f);

    for (int base = beg; base < end; base += 32) {
        int cnt = end - base; if (cnt > 32) cnt = 32;
        int myi = g_nidx[base + ((lane < cnt) ? lane : 0)];
        int k = 0;
        for (; k + 2 <= cnt; k += 2) {
            int e0 = __shfl_sync(0xffffffffu, myi, k);
            int e1 = __shfl_sync(0xffffffffu, myi, k + 1);
            uint2 u0 = *(const uint2*)(g_heattr_h + (size_t)e0 * 64 + lane * 2);
            uint2 u1 = *(const uint2*)(g_heattr_h + (size_t)e1 * 64 + lane * 2);
            acc_bf16x2(a0, u0);
            acc_bf16x2(a1, u1);
        }
        if (k < cnt) {
            int e0 = __shfl_sync(0xffffffffu, myi, k);
            uint2 u0 = *(const uint2*)(g_heattr_h + (size_t)e0 * 64 + lane * 2);
            acc_bf16x2(a0, u0);
        }
    }

    float s = 1.0f / ((float)(end - beg) + EPS);
    float4 xn = ((const float4*)g_xnode)[(size_t)w * 32 + lane];
    float4 b  = ((const float4*)bias)[lane];
    float4 o;
    o.x = (a0.x + a1.x) * s + xn.x + b.x;
    o.y = (a0.y + a1.y) * s + xn.y + b.y;
    o.z = (a0.z + a1.z) * s + xn.z + b.z;
    o.w = (a0.w + a1.w) * s + xn.w + b.w;
    ((float4*)out)[(size_t)w * 32 + lane] = o;
}

// ---------------- launch -----------------------------------------------------
extern "C" void kernel_launch(void* const* d_in, const int* in_sizes, int n_in,
                              void* d_out, int out_size) {
    const float* x    = (const float*)d_in[0];
    const void*  hidx = d_in[1];
    const float* W    = (const float*)d_in[2];
    const float* bias = (const float*)d_in[3];
    float* out = (float*)d_out;

    int N   = in_sizes[0] / D;
    int nnz = in_sizes[1] / 2;
    int q = (nnz + 3) / 4;

    static cudaStream_t s2 = 0, s3 = 0;
    static cudaEvent_t evA = 0, evI = 0, evG = 0, evN = 0;
    static int* p_ecnt; static int* p_ncnt;
    static int* p_eoff; static int* p_noff;
    if (!s2) {
        cudaStreamCreateWithFlags(&s2, cudaStreamNonBlocking);
        cudaStreamCreateWithFlags(&s3, cudaStreamNonBlocking);
        cudaEventCreateWithFlags(&evA, cudaEventDisableTiming);
        cudaEventCreateWithFlags(&evI, cudaEventDisableTiming);
        cudaEventCreateWithFlags(&evG, cudaEventDisableTiming);
        cudaEventCreateWithFlags(&evN, cudaEventDisableTiming);
        cudaFuncSetAttribute(gemm_kernel,
                             cudaFuncAttributeMaxDynamicSharedMemorySize, GEMM_SMEM);
        void* tmp;
        cudaGetSymbolAddress(&tmp, g_cnts); p_ecnt = (int*)tmp; p_ncnt = p_ecnt + E_CAP;
        cudaGetSymbolAddress(&tmp, g_eoff); p_eoff = (int*)tmp;
        cudaGetSymbolAddress(&tmp, g_noff); p_noff = (int*)tmp;
    }

    // 1: GEMM forked immediately
    cudaEventRecord(evA, 0);
    cudaStreamWaitEvent(s2, evA, 0);
    gemm_kernel<<<(N + 127) / 128, 256, GEMM_SMEM, s2>>>(x, W, N);
    cudaEventRecord(evG, s2);

    // 2-5: edge-side CSR chain on capture stream (critical path)
    init_e_kernel<<<E_CAP / 4 / 256, 256>>>((const int*)hidx);
    cudaEventRecord(evI, 0);
    hist_e_kernel<<<(q + 255) / 256, 256>>>(hidx, nnz);
    scan_fused_kernel<16><<<1, 1024>>>(p_ecnt, p_eoff, p_ecnt, E_CAP);
    fill_e_kernel<<<(q + 255) / 256, 256>>>(hidx, nnz);

    // 6: edge_agg (ncu -s 5 -c 1 should capture this launch)
    edge_agg_kernel<<<E_CAP / 8, 256>>>();

    // node-side CSR on s3 (hidden; needs is64 from init_e)
    cudaStreamWaitEvent(s3, evI, 0);
    init_n_kernel<<<N_CAP / 4 / 256, 256, 0, s3>>>();
    hist_n_kernel<<<(q + 255) / 256, 256, 0, s3>>>(hidx, nnz);
    scan_fused_kernel<64><<<1, 1024, 0, s3>>>(p_ncnt, p_noff, p_ncnt, N_CAP);
    fill_n_kernel<<<(q + 255) / 256, 256, 0, s3>>>(hidx, nnz);
    cudaEventRecord(evN, s3);

    // node_agg needs: heattr (stream order), node CSR (evN), residual (evG)
    cudaStreamWaitEvent(0, evN, 0);
    cudaStreamWaitEvent(0, evG, 0);
    node_agg_kernel<<<(N + 7) / 8, 256>>>(bias, out, N);
}

// round 13
// speedup vs baseline: 1.0443x; 1.0149x over previous
#include <cuda_runtime.h>
#include <cuda_bf16.h>
#include <stdint.h>

#define D 128
#define E_CAP 16384
#define N_CAP 65536
#define NNZ_CAP (1 << 20)
#define EPS 1e-8f
#define CHUNK 4096
#define NBLK_E (E_CAP / CHUNK)            // 4

// ---------------- scratch (static device globals; no allocation) ------------
__device__ float    g_xnode[(size_t)N_CAP * D];      // fp32 x@W^T (exact residual)
__device__ unsigned g_xnode_h[(size_t)N_CAP * 64];   // bf16x2 gather mirror
__device__ unsigned g_heattr_h[(size_t)E_CAP * 64];  // bf16x2 hyperedge attr
__device__ int g_eidx[NNZ_CAP];
__device__ int g_nidx[NNZ_CAP];
__device__ int g_eoff[E_CAP + 1];
__device__ int g_noff[N_CAP + 1];
__device__ int g_cnts[E_CAP + N_CAP];                // counts, then reused as cursors
__device__ int g_bsum[NBLK_E];
__device__ int g_is64;

#define ECNT (g_cnts)
#define NCNT (g_cnts + E_CAP)

// ---------------- inits: zero counters (per side) + dtype detect -------------
__global__ void init_e_kernel(const int* __restrict__ h) {
    int i = blockIdx.x * blockDim.x + threadIdx.x;
    ((int4*)ECNT)[i] = make_int4(0, 0, 0, 0);
    if (i == 0)
        g_is64 = (h[1] == 0 && h[3] == 0 && h[5] == 0 && h[7] == 0) ? 1 : 0;
}

__global__ void init_n_kernel() {
    int i = blockIdx.x * blockDim.x + threadIdx.x;
    ((int4*)NCNT)[i] = make_int4(0, 0, 0, 0);
}

// ---------------- histograms (4 entries / thread), per side ------------------
__global__ __launch_bounds__(256) void hist_e_kernel(const void* __restrict__ base, int nnz) {
    int i0 = (blockIdx.x * blockDim.x + threadIdx.x) * 4;
    if (i0 >= nnz) return;
    int m = nnz - i0; if (m > 4) m = 4;
    int e[4];
    if (g_is64) {
        const long long* p = (const long long*)base + nnz;
        #pragma unroll
        for (int k = 0; k < 4; k++) e[k] = (int)__ldg(p + i0 + ((k < m) ? k : 0));
    } else {
        const int* p = (const int*)base + nnz;
        #pragma unroll
        for (int k = 0; k < 4; k++) e[k] = __ldg(p + i0 + ((k < m) ? k : 0));
    }
    #pragma unroll
    for (int k = 0; k < 4; k++)
        if (k < m) atomicAdd(&ECNT[e[k]], 1);
}

__global__ __launch_bounds__(256) void hist_n_kernel(const void* __restrict__ base, int nnz) {
    int i0 = (blockIdx.x * blockDim.x + threadIdx.x) * 4;
    if (i0 >= nnz) return;
    int m = nnz - i0; if (m > 4) m = 4;
    int s[4];
    if (g_is64) {
        const long long* p = (const long long*)base;
        #pragma unroll
        for (int k = 0; k < 4; k++) s[k] = (int)__ldg(p + i0 + ((k < m) ? k : 0));
    } else {
        const int* p = (const int*)base;
        #pragma unroll
        for (int k = 0; k < 4; k++) s[k] = __ldg(p + i0 + ((k < m) ? k : 0));
    }
    #pragma unroll
    for (int k = 0; k < 4; k++)
        if (k < m) atomicAdd(&NCNT[s[k]], 1);
}

// ---------------- edge scan: 4-block local scan + fixup (R10 form) -----------
__global__ __launch_bounds__(1024) void scan_e_local_kernel() {
    int b = blockIdx.x;
    int lo = b * CHUNK;

    __shared__ int wsum[32];
    int tid = threadIdx.x, lane = tid & 31, wid = tid >> 5;
    int idx = lo + tid * 4;

    int4 v = *(const int4*)(ECNT + idx);
    int tsum = v.x + v.y + v.z + v.w;
    int incl = tsum;
    #pragma unroll
    for (int s = 1; s < 32; s <<= 1) {
        int t = __shfl_up_sync(0xffffffffu, incl, s);
        if (lane >= s) incl += t;
    }
    if (lane == 31) wsum[wid] = incl;
    __syncthreads();
    if (wid == 0) {
        int w = wsum[lane];
        int wi = w;
        #pragma unroll
        for (int s = 1; s < 32; s <<= 1) {
            int t = __shfl_up_sync(0xffffffffu, wi, s);
            if (lane >= s) wi += t;
        }
        wsum[lane] = wi - w;
    }
    __syncthreads();
    int ex = wsum[wid] + incl - tsum;
    g_eoff[idx]     = ex;
    g_eoff[idx + 1] = ex + v.x;
    g_eoff[idx + 2] = ex + v.x + v.y;
    g_eoff[idx + 3] = ex + v.x + v.y + v.z;
    if (tid == 1023) g_bsum[b] = ex + tsum;
}

__global__ __launch_bounds__(1024) void scan_e_fixup_kernel() {
    int b = blockIdx.x;
    __shared__ int s_base;
    int tid = threadIdx.x;
    if (tid == 0) {
        int base = 0;
        for (int i = 0; i < b; i++) base += g_bsum[i];
        s_base = base;
    }
    __syncthreads();
    int base = s_base;
    int idx = b * CHUNK + tid * 4;
    int4 o = *(int4*)(g_eoff + idx);
    o.x += base; o.y += base; o.z += base; o.w += base;
    *(int4*)(g_eoff + idx) = o;
    *(int4*)(ECNT + idx) = o;   // cursors start at segment start
    if (tid == 0 && b == NBLK_E - 1) g_eoff[E_CAP] = base + g_bsum[b];
}

// ---------------- node scan: fused single-block (hidden on s3) ---------------
template <int SEG>
__global__ __launch_bounds__(1024) void scan_fused_kernel(const int* __restrict__ cnt,
                                                          int* __restrict__ off,
                                                          int* __restrict__ cur,
                                                          int count) {
    __shared__ int wsum[32];
    int tid = threadIdx.x, lane = tid & 31, wid = tid >> 5;
    int base = tid * SEG;

    int v[SEG];
    #pragma unroll
    for (int i = 0; i < SEG / 4; i++)
        *(int4*)(v + i * 4) = *(const int4*)(cnt + base + i * 4);

    int tsum = 0;
    #pragma unroll
    for (int i = 0; i < SEG; i++) tsum += v[i];

    int incl = tsum;
    #pragma unroll
    for (int s = 1; s < 32; s <<= 1) {
        int t = __shfl_up_sync(0xffffffffu, incl, s);
        if (lane >= s) incl += t;
    }
    if (lane == 31) wsum[wid] = incl;
    __syncthreads();
    if (wid == 0) {
        int w = wsum[lane];
        int wi = w;
        #pragma unroll
        for (int s = 1; s < 32; s <<= 1) {
            int t = __shfl_up_sync(0xffffffffu, wi, s);
            if (lane >= s) wi += t;
        }
        wsum[lane] = wi - w;
    }
    __syncthreads();
    int ex = wsum[wid] + incl - tsum;

    int o[SEG];
    int run = ex;
    #pragma unroll
    for (int i = 0; i < SEG; i++) { o[i] = run; run += v[i]; }

    #pragma unroll
    for (int i = 0; i < SEG / 4; i++) {
        int4 w4 = *(int4*)(o + i * 4);
        *(int4*)(off + base + i * 4) = w4;
        *(int4*)(cur + base + i * 4) = w4;
    }
    if (tid == 1023) off[count] = run;
}

// ---------------- bucket fills (cursor atomics, 4/thread), per side ----------
__global__ __launch_bounds__(256) void fill_e_kernel(const void* __restrict__ base, int nnz) {
    int i0 = (blockIdx.x * blockDim.x + threadIdx.x) * 4;
    if (i0 >= nnz) return;
    int m = nnz - i0; if (m > 4) m = 4;
    int src[4], e[4];
    if (g_is64) {
        const long long* p = (const long long*)base;
        #pragma unroll
        for (int k = 0; k < 4; k++) {
            int i = i0 + ((k < m) ? k : 0);
            src[k] = (int)__ldg(p + i);
            e[k]   = (int)__ldg(p + nnz + i);
        }
    } else {
        const int* p = (const int*)base;
        #pragma unroll
        for (int k = 0; k < 4; k++) {
            int i = i0 + ((k < m) ? k : 0);
            src[k] = __ldg(p + i);
            e[k]   = __ldg(p + nnz + i);
        }
    }
    #pragma unroll
    for (int k = 0; k < 4; k++) {
        if (k < m) {
            int pe = atomicAdd(&ECNT[e[k]], 1);
            g_eidx[pe] = src[k];
        }
    }
}

__global__ __launch_bounds__(256) void fill_n_kernel(const void* __restrict__ base, int nnz) {
    int i0 = (blockIdx.x * blockDim.x + threadIdx.x) * 4;
    if (i0 >= nnz) return;
    int m = nnz - i0; if (m > 4) m = 4;
    int src[4], e[4];
    if (g_is64) {
        const long long* p = (const long long*)base;
        #pragma unroll
        for (int k = 0; k < 4; k++) {
            int i = i0 + ((k < m) ? k : 0);
            src[k] = (int)__ldg(p + i);
            e[k]   = (int)__ldg(p + nnz + i);
        }
    } else {
        const int* p = (const int*)base;
        #pragma unroll
        for (int k = 0; k < 4; k++) {
            int i = i0 + ((k < m) ? k : 0);
            src[k] = __ldg(p + i);
            e[k]   = __ldg(p + nnz + i);
        }
    }
    #pragma unroll
    for (int k = 0; k < 4; k++) {
        if (k < m) {
            int pn = atomicAdd(&NCNT[src[k]], 1);
            g_nidx[pn] = e[k];
        }
    }
}

// ---------------- GEMM: g_xnode = x @ W^T, 128x128 tile, 8x8/thread ----------
#define WT_STRIDE 132
#define GEMM_SMEM ((128 * WT_STRIDE + 128 * WT_STRIDE) * 4)   // 135168 B

__device__ __forceinline__ unsigned long long fma2(unsigned long long a,
                                                   unsigned long long b,
                                                   unsigned long long c) {
    unsigned long long d;
    asm("fma.rn.f32x2 %0, %1, %2, %3;" : "=l"(d) : "l"(a), "l"(b), "l"(c));
    return d;
}

__global__ __launch_bounds__(256, 1) void gemm_kernel(const float* __restrict__ x,
                                                      const float* __restrict__ W,
                                                      int N) {
    extern __shared__ float sm[];
    float* WT = sm;                        // [128][132], WT[k][j] = W[j][k]
    float* Xs = sm + 128 * WT_STRIDE;      // [128][132]

    int t = threadIdx.x;
    int row0 = blockIdx.x * 128;

    #pragma unroll
    for (int i = 0; i < 64; i++) {
        int idx = t + i * 256;
        int j = idx >> 7, k = idx & 127;
        WT[k * WT_STRIDE + j] = W[idx];
    }
    #pragma unroll
    for (int i = 0; i < 64; i++) {
        int idx = t + i * 256;
        int r = idx >> 7, k = idx & 127;
        int row = row0 + r;
        if (row >= N) row = N - 1;
        Xs[r * WT_STRIDE + k] = x[(size_t)row * D + k];
    }
    __syncthreads();

    int tx = t & 15, ty = t >> 4;
    int c0 = tx * 8, r0 = ty * 8;

    unsigned long long acc[8][4];
    #pragma unroll
    for (int i = 0; i < 8; i++)
        #pragma unroll
        for (int j = 0; j < 4; j++) acc[i][j] = 0ull;

    #pragma unroll 2
    for (int k = 0; k < 128; k++) {
        ulonglong2 wa = *(const ulonglong2*)(WT + k * WT_STRIDE + c0);
        ulonglong2 wb = *(const ulonglong2*)(WT + k * WT_STRIDE + c0 + 4);
        #pragma unroll
        for (int i = 0; i < 8; i++) {
            unsigned au = __float_as_uint(Xs[(r0 + i) * WT_STRIDE + k]);
            unsigned long long aa;
            asm("mov.b64 %0, {%1, %1};" : "=l"(aa) : "r"(au));
            acc[i][0] = fma2(aa, wa.x, acc[i][0]);
            acc[i][1] = fma2(aa, wa.y, acc[i][1]);
            acc[i][2] = fma2(aa, wb.x, acc[i][2]);
            acc[i][3] = fma2(aa, wb.y, acc[i][3]);
        }
    }

    #pragma unroll
    for (int i = 0; i < 8; i++) {
        int row = row0 + r0 + i;
        if (row < N) {
            ulonglong2 o0; o0.x = acc[i][0]; o0.y = acc[i][1];
            ulonglong2 o1; o1.x = acc[i][2]; o1.y = acc[i][3];
            *(ulonglong2*)(g_xnode + (size_t)row * D + c0)     = o0;
            *(ulonglong2*)(g_xnode + (size_t)row * D + c0 + 4) = o1;
            uint4 h;
            #pragma unroll
            for (int j = 0; j < 4; j++) {
                unsigned lo, hi;
                asm("mov.b64 {%0, %1}, %2;" : "=r"(lo), "=r"(hi) : "l"(acc[i][j]));
                unsigned r2;
                asm("cvt.rn.bf16x2.f32 %0, %1, %2;" : "=r"(r2)
                    : "f"(__uint_as_float(hi)), "f"(__uint_as_float(lo)));
                ((unsigned*)&h)[j] = r2;
            }
            *(uint4*)(g_xnode_h + (size_t)row * 64 + tx * 4) = h;
        }
    }
}

// ---------------- bf16x2 pair accumulate helper ------------------------------
__device__ __forceinline__ void acc_bf16x2(float4& a, uint2 u) {
    a.x += __uint_as_float(u.x << 16);
    a.y += __uint_as_float(u.x & 0xffff0000u);
    a.z += __uint_as_float(u.y << 16);
    a.w += __uint_as_float(u.y & 0xffff0000u);
}

// ---------------- phase A: warp-per-edge, shfl-distributed indices (R10) -----
__global__ __launch_bounds__(256) void edge_agg_kernel() {
    int w = (blockIdx.x * blockDim.x + threadIdx.x) >> 5;  // edge id
    int lane = threadIdx.x & 31;
    int beg = g_eoff[w], end = g_eoff[w + 1];
    if (beg == end) return;

    float4 a0 = make_float4(0.f, 0.f, 0.f, 0.f);
    float4 a1 = make_float4(0.f, 0.f, 0.f, 0.f);

    for (int base = beg; base < end; base += 32) {
        int cnt = end - base; if (cnt > 32) cnt = 32;
        int myi = g_eidx[base + ((lane < cnt) ? lane : 0)];
        int k = 0;
        for (; k + 2 <= cnt; k += 2) {
            int n0 = __shfl_sync(0xffffffffu, myi, k);
            int n1 = __shfl_sync(0xffffffffu, myi, k + 1);
            uint2 u0 = *(const uint2*)(g_xnode_h + (size_t)n0 * 64 + lane * 2);
            uint2 u1 = *(const uint2*)(g_xnode_h + (size_t)n1 * 64 + lane * 2);
            acc_bf16x2(a0, u0);
            acc_bf16x2(a1, u1);
        }
        if (k < cnt) {
            int n0 = __shfl_sync(0xffffffffu, myi, k);
            uint2 u0 = *(const uint2*)(g_xnode_h + (size_t)n0 * 64 + lane * 2);
            acc_bf16x2(a0, u0);
        }
    }

    float inv = 1.0f / ((float)(end - beg) + EPS);
    float f0 = (a0.x + a1.x) * inv;
    float f1 = (a0.y + a1.y) * inv;
    float f2 = (a0.z + a1.z) * inv;
    float f3 = (a0.w + a1.w) * inv;
    uint2 r;
    asm("cvt.rn.bf16x2.f32 %0, %1, %2;" : "=r"(r.x) : "f"(f1), "f"(f0));
    asm("cvt.rn.bf16x2.f32 %0, %1, %2;" : "=r"(r.y) : "f"(f3), "f"(f2));
    *(uint2*)(g_heattr_h + (size_t)w * 64 + lane * 2) = r;
}

// ---------------- phase B: warp-per-node, shfl indices + fused finalize (R10)-
__global__ __launch_bounds__(256) void node_agg_kernel(const float* __restrict__ bias,
                                                       float* __restrict__ out,
                                                       int N) {
    int w = (blockIdx.x * blockDim.x + threadIdx.x) >> 5;
    if (w >= N) return;
    int lane = threadIdx.x & 31;
    int beg = g_noff[w], end = g_noff[w + 1];

    float4 a0 = make_float4(0.f, 0.f, 0.f, 0.f);
    float4 a1 = make_float4(0.f, 0.f, 0.f, 0.f);

    for (int base = beg; base < end; base += 32) {
        int cnt = end - base; if (cnt > 32) cnt = 32;
        int myi = g_nidx[base + ((lane < cnt) ? lane : 0)];
        int k = 0;
        for (; k + 2 <= cnt; k += 2) {
            int e0 = __shfl_sync(0xffffffffu, myi, k);
            int e1 = __shfl_sync(0xffffffffu, myi, k + 1);
            uint2 u0 = *(const uint2*)(g_heattr_h + (size_t)e0 * 64 + lane * 2);
            uint2 u1 = *(const uint2*)(g_heattr_h + (size_t)e1 * 64 + lane * 2);
            acc_bf16x2(a0, u0);
            acc_bf16x2(a1, u1);
        }
        if (k < cnt) {
            int e0 = __shfl_sync(0xffffffffu, myi, k);
            uint2 u0 = *(const uint2*)(g_heattr_h + (size_t)e0 * 64 + lane * 2);
            acc_bf16x2(a0, u0);
        }
    }

    float s = 1.0f / ((float)(end - beg) + EPS);
    float4 xn = ((const float4*)g_xnode)[(size_t)w * 32 + lane];
    float4 b  = ((const float4*)bias)[lane];
    float4 o;
    o.x = (a0.x + a1.x) * s + xn.x + b.x;
    o.y = (a0.y + a1.y) * s + xn.y + b.y;
    o.z = (a0.z + a1.z) * s + xn.z + b.z;
    o.w = (a0.w + a1.w) * s + xn.w + b.w;
    ((float4*)out)[(size_t)w * 32 + lane] = o;
}

// ---------------- launch -----------------------------------------------------
extern "C" void kernel_launch(void* const* d_in, const int* in_sizes, int n_in,
                              void* d_out, int out_size) {
    const float* x    = (const float*)d_in[0];
    const void*  hidx = d_in[1];
    const float* W    = (const float*)d_in[2];
    const float* bias = (const float*)d_in[3];
    float* out = (float*)d_out;

    int N   = in_sizes[0] / D;
    int nnz = in_sizes[1] / 2;
    int q = (nnz + 3) / 4;

    static cudaStream_t s2 = 0, s3 = 0;
    static cudaEvent_t evA = 0, evI = 0, evG = 0, evN = 0;
    static int* p_ncnt; static int* p_noff;
    if (!s2) {
        cudaStreamCreateWithFlags(&s2, cudaStreamNonBlocking);
        cudaStreamCreateWithFlags(&s3, cudaStreamNonBlocking);
        cudaEventCreateWithFlags(&evA, cudaEventDisableTiming);
        cudaEventCreateWithFlags(&evI, cudaEventDisableTiming);
        cudaEventCreateWithFlags(&evG, cudaEventDisableTiming);
        cudaEventCreateWithFlags(&evN, cudaEventDisableTiming);
        cudaFuncSetAttribute(gemm_kernel,
                             cudaFuncAttributeMaxDynamicSharedMemorySize, GEMM_SMEM);
        void* tmp;
        cudaGetSymbolAddress(&tmp, g_cnts); p_ncnt = (int*)tmp + E_CAP;
        cudaGetSymbolAddress(&tmp, g_noff); p_noff = (int*)tmp;
    }

    // GEMM forked immediately (produces g_xnode + g_xnode_h)
    cudaEventRecord(evA, 0);
    cudaStreamWaitEvent(s2, evA, 0);
    gemm_kernel<<<(N + 127) / 128, 256, GEMM_SMEM, s2>>>(x, W, N);
    cudaEventRecord(evG, s2);

    // edge-side CSR chain on capture stream (critical path)
    init_e_kernel<<<E_CAP / 4 / 256, 256>>>((const int*)hidx);
    cudaEventRecord(evI, 0);
    hist_e_kernel<<<(q + 255) / 256, 256>>>(hidx, nnz);
    scan_e_local_kernel<<<NBLK_E, 1024>>>();
    scan_e_fixup_kernel<<<NBLK_E, 1024>>>();
    fill_e_kernel<<<(q + 255) / 256, 256>>>(hidx, nnz);
    edge_agg_kernel<<<E_CAP / 8, 256>>>();

    // node-side CSR on s3 (hidden; needs is64 from init_e)
    cudaStreamWaitEvent(s3, evI, 0);
    init_n_kernel<<<N_CAP / 4 / 256, 256, 0, s3>>>();
    hist_n_kernel<<<(q + 255) / 256, 256, 0, s3>>>(hidx, nnz);
    scan_fused_kernel<64><<<1, 1024, 0, s3>>>(p_ncnt, p_noff, p_ncnt, N_CAP);
    fill_n_kernel<<<(q + 255) / 256, 256, 0, s3>>>(hidx, nnz);
    cudaEventRecord(evN, s3);

    // node_agg needs: heattr (stream order), node CSR (evN), residual (evG)
    cudaStreamWaitEvent(0, evN, 0);
    cudaStreamWaitEvent(0, evG, 0);
    node_agg_kernel<<<(N + 7) / 8, 256>>>(bias, out, N);
}